// round 2
// baseline (speedup 1.0000x reference)
#include <cuda_runtime.h>
#include <math.h>

// ---------------------------------------------------------------------------
// Problem constants (shapes are fixed by the dataset)
// ---------------------------------------------------------------------------
#define D      768
#define BATCH  64
#define TP1    257            // T+1
#define TFEAT  256
#define KC     512
#define KF     4096
#define KTOT   4608            // KC + KF
#define NROWS  16448           // TP1 * BATCH
#define NFEATR 16384           // TFEAT * BATCH

// Output layout (float32 elements):
//   [0]                      loss (1)
//   [1 .. 1+12632064)        quantized_features [257,64,768]
//   [12632065]               perplexity (1)
//   [12632066 .. +16448)     encoding_indices [257*64]
//   [12648514 .. +75792384)  distances [64,257,4608]
#define OFF_QF    1LL
#define OFF_PERP  12632065LL
#define OFF_IDX   12632066LL
#define OFF_DIST  12648514LL

#define FMAXV 3.402823466e+38f

// ---------------------------------------------------------------------------
// Scratch (device globals -- no allocation allowed)
// ---------------------------------------------------------------------------
__device__ float g_x2[NROWS];        // ||x||^2 per flattened feature row
__device__ float g_e2[KTOT];         // ||e||^2: class at [0,512), feat at [512,4608)
__device__ float g_rowerr[NROWS];    // per-row sum (quantized - x)^2
__device__ int   g_counts[KTOT];     // codebook usage counts

// ---------------------------------------------------------------------------
// 0) zero counters (must be re-zeroed on every graph replay)
// ---------------------------------------------------------------------------
__global__ void k_zero() {
    int i = blockIdx.x * 256 + threadIdx.x;
    if (i < KTOT) g_counts[i] = 0;
}

// ---------------------------------------------------------------------------
// 1) row squared norms: one warp per row
//    rows [0,16448): features; [16448,16960): class cb; [16960,21056): feat cb
// ---------------------------------------------------------------------------
__global__ void k_rownorms(const float* __restrict__ feats,
                           const float* __restrict__ ccb,
                           const float* __restrict__ fcb) {
    int gw   = (blockIdx.x * blockDim.x + threadIdx.x) >> 5;
    int lane = threadIdx.x & 31;
    if (gw >= NROWS + KC + KF) return;
    const float* p;
    float* o;
    if (gw < NROWS)            { p = feats + (size_t)gw * D;            o = &g_x2[gw]; }
    else if (gw < NROWS + KC)  { p = ccb + (size_t)(gw - NROWS) * D;    o = &g_e2[gw - NROWS]; }
    else                       { p = fcb + (size_t)(gw - NROWS - KC) * D; o = &g_e2[KC + gw - NROWS - KC]; }
    float s = 0.f;
    for (int j = lane; j < D; j += 32) { float v = p[j]; s = fmaf(v, v, s); }
    #pragma unroll
    for (int off = 16; off; off >>= 1) s += __shfl_down_sync(0xFFFFFFFFu, s, off);
    if (lane == 0) *o = s;
}

// ---------------------------------------------------------------------------
// 2) FMAX padding fill for the distances tensor
//    class rows (t=0): k in [512,4608)  -> 64*4096  = 262144 elems
//    feat  rows (t>0): k in [0,512)     -> 16384*512 = 8388608 elems
// ---------------------------------------------------------------------------
__global__ void k_fill_fmax(float* __restrict__ out) {
    float* dist = out + OFF_DIST;
    long long i = (long long)blockIdx.x * 256 + threadIdx.x;
    if (i < 262144LL) {
        int b = (int)(i >> 12);
        int k = KC + (int)(i & 4095);
        dist[(size_t)b * TP1 * KTOT + k] = FMAXV;
        return;
    }
    long long j = i - 262144LL;
    if (j < 8388608LL) {
        int rr = (int)(j >> 9);
        int k  = (int)(j & 511);
        int b  = rr & 63;
        int t  = (rr >> 6) + 1;
        dist[((size_t)b * TP1 + t) * KTOT + k] = FMAXV;
    }
}

// ---------------------------------------------------------------------------
// 3) Distance GEMM: dist = x2 + e2 - 2 * A @ B^T
//    Classic 128x128x16 SGEMM, 256 threads, 8x8 register micro-tile,
//    float4 shared loads (avoids stride-8 LDS bank-conflict tax).
//    Writes directly into the permuted/padded output distance tensor.
// ---------------------------------------------------------------------------
__global__ __launch_bounds__(256) void k_gemm_dist(
    const float* __restrict__ A,   // [M, 768]
    const float* __restrict__ B,   // [N, 768]
    float* __restrict__ out,
    int M, int N, int x2off, int e2off, int isClass)
{
    __shared__ float As[16][128];
    __shared__ float Bs[16][128];
    const int tid = threadIdx.x;
    const int m0 = blockIdx.y * 128;
    const int n0 = blockIdx.x * 128;
    const int ty = tid >> 4, tx = tid & 15;

    float acc[8][8];
    #pragma unroll
    for (int i = 0; i < 8; i++)
        #pragma unroll
        for (int j = 0; j < 8; j++) acc[i][j] = 0.f;

    for (int d0 = 0; d0 < D; d0 += 16) {
        #pragma unroll
        for (int i = 0; i < 2; i++) {
            int lin = tid + i * 256;
            int row = lin >> 2;
            int c4  = (lin & 3) * 4;
            float4 va = make_float4(0.f, 0.f, 0.f, 0.f);
            float4 vb = make_float4(0.f, 0.f, 0.f, 0.f);
            if (m0 + row < M) va = *(const float4*)(A + (size_t)(m0 + row) * D + d0 + c4);
            if (n0 + row < N) vb = *(const float4*)(B + (size_t)(n0 + row) * D + d0 + c4);
            As[c4 + 0][row] = va.x; As[c4 + 1][row] = va.y;
            As[c4 + 2][row] = va.z; As[c4 + 3][row] = va.w;
            Bs[c4 + 0][row] = vb.x; Bs[c4 + 1][row] = vb.y;
            Bs[c4 + 2][row] = vb.z; Bs[c4 + 3][row] = vb.w;
        }
        __syncthreads();
        #pragma unroll
        for (int d = 0; d < 16; d++) {
            float4 a0 = *(const float4*)&As[d][ty * 8];
            float4 a1 = *(const float4*)&As[d][ty * 8 + 4];
            float4 b0 = *(const float4*)&Bs[d][tx * 8];
            float4 b1 = *(const float4*)&Bs[d][tx * 8 + 4];
            float ra[8] = {a0.x, a0.y, a0.z, a0.w, a1.x, a1.y, a1.z, a1.w};
            float rb[8] = {b0.x, b0.y, b0.z, b0.w, b1.x, b1.y, b1.z, b1.w};
            #pragma unroll
            for (int i = 0; i < 8; i++)
                #pragma unroll
                for (int j = 0; j < 8; j++)
                    acc[i][j] = fmaf(ra[i], rb[j], acc[i][j]);
        }
        __syncthreads();
    }

    float* dist = out + OFF_DIST;
    #pragma unroll
    for (int i = 0; i < 8; i++) {
        int n = m0 + ty * 8 + i;
        if (n >= M) return;
        float xn = g_x2[x2off + n];
        size_t base;
        if (isClass) {
            base = (size_t)n * TP1 * KTOT;                  // b=n, t=0, k-offset 0
        } else {
            int t = n >> 6, b = n & 63;
            base = ((size_t)b * TP1 + (t + 1)) * KTOT + KC; // feat block starts at k=512
        }
        #pragma unroll
        for (int j2 = 0; j2 < 4; j2++) {
            int k = n0 + tx * 8 + j2 * 2;
            float2 o;
            o.x = xn + g_e2[e2off + k]     - 2.f * acc[i][j2 * 2];
            o.y = xn + g_e2[e2off + k + 1] - 2.f * acc[i][j2 * 2 + 1];
            *(float2*)(dist + base + k) = o;   // region is 8B-aligned, not 16B
        }
    }
}

// ---------------------------------------------------------------------------
// 4) Per-row argmin (first-occurrence tie-break) + gather + per-row sq-error
//    One 256-thread block per row.
// ---------------------------------------------------------------------------
__global__ __launch_bounds__(256) void k_argmin_gather(
    const float* __restrict__ feats,
    const float* __restrict__ ccb,
    const float* __restrict__ fcb,
    float* __restrict__ out)
{
    const int r = blockIdx.x;
    const int tid = threadIdx.x;
    const float* dist = out + OFF_DIST;

    const float* rowp; const float* cb;
    int K, flatrow, idx_add;
    if (r < BATCH) {
        K = KC; rowp = dist + (size_t)r * TP1 * KTOT;
        cb = ccb; flatrow = r; idx_add = 0;
    } else {
        int rr = r - BATCH;
        int t = rr >> 6, b = rr & 63;
        K = KF; rowp = dist + ((size_t)b * TP1 + (t + 1)) * KTOT + KC;
        cb = fcb; flatrow = BATCH + rr; idx_add = KC;
    }

    float best = FMAXV;
    int bidx = K;
    for (int k = tid; k < K; k += 256) {
        float v = rowp[k];
        if (v < best) { best = v; bidx = k; }
    }

    __shared__ float sv[256];
    __shared__ int   si[256];
    sv[tid] = best; si[tid] = bidx;
    __syncthreads();
    #pragma unroll
    for (int s = 128; s > 0; s >>= 1) {
        if (tid < s) {
            float v2 = sv[tid + s]; int i2 = si[tid + s];
            if (v2 < sv[tid] || (v2 == sv[tid] && i2 < si[tid])) { sv[tid] = v2; si[tid] = i2; }
        }
        __syncthreads();
    }
    const int li = si[0];

    // gather codebook row -> quantized_features; accumulate (code - x)^2
    const float* code = cb + (size_t)li * D;
    const float* x    = feats + (size_t)flatrow * D;
    float* qf = out + OFF_QF + (size_t)flatrow * D;
    float err = 0.f;
    for (int d = tid; d < D; d += 256) {
        float c = code[d];
        qf[d] = c;
        float dd = c - x[d];
        err = fmaf(dd, dd, err);
    }
    __shared__ float se[256];
    se[tid] = err;
    __syncthreads();
    #pragma unroll
    for (int s = 128; s > 0; s >>= 1) {
        if (tid < s) se[tid] += se[tid + s];
        __syncthreads();
    }
    if (tid == 0) {
        g_rowerr[r] = se[0];
        out[OFF_IDX + r] = (float)(li + idx_add);
        atomicAdd(&g_counts[idx_add + li], 1);
    }
}

// ---------------------------------------------------------------------------
// 5) Finalize: loss and perplexity (deterministic double reductions)
// ---------------------------------------------------------------------------
__global__ __launch_bounds__(256) void k_finalize(float* __restrict__ out) {
    __shared__ double sh[256];
    const int tid = threadIdx.x;
    double res[4];

    // pass 0: class sq-err, 1: feat sq-err, 2: class entropy, 3: feat entropy
    for (int pass = 0; pass < 4; pass++) {
        double s = 0.0;
        if (pass == 0) {
            for (int r = tid; r < BATCH; r += 256) s += (double)g_rowerr[r];
        } else if (pass == 1) {
            for (int r = BATCH + tid; r < NROWS; r += 256) s += (double)g_rowerr[r];
        } else if (pass == 2) {
            for (int k = tid; k < KC; k += 256) {
                double p = (double)g_counts[k] / (double)BATCH;
                s += p * log(p + 1e-10);
            }
        } else {
            for (int k = tid; k < KF; k += 256) {
                double p = (double)g_counts[KC + k] / (double)NFEATR;
                s += p * log(p + 1e-10);
            }
        }
        sh[tid] = s;
        __syncthreads();
        for (int st = 128; st > 0; st >>= 1) {
            if (tid < st) sh[tid] += sh[tid + st];
            __syncthreads();
        }
        res[pass] = sh[0];
        __syncthreads();
    }

    if (tid == 0) {
        double mean_c = res[0] / (double)(1 * BATCH * D);
        double mean_f = res[1] / (double)(TFEAT * BATCH * D);
        out[0]        = (float)(0.25 * (mean_c + mean_f));
        out[OFF_PERP] = (float)(exp(-res[2]) + exp(-res[3]));
    }
}

// ---------------------------------------------------------------------------
// Launch
// ---------------------------------------------------------------------------
extern "C" void kernel_launch(void* const* d_in, const int* in_sizes, int n_in,
                              void* d_out, int out_size) {
    const float* feats = (const float*)d_in[0];   // [257,64,768]
    const float* ccb   = (const float*)d_in[1];   // [512,768]
    const float* fcb   = (const float*)d_in[2];   // [4096,768]
    float* out = (float*)d_out;

    // 0) zero codebook counters (graph replays reuse them)
    k_zero<<<(KTOT + 255) / 256, 256>>>();

    // 1) row norms: 21056 rows, one warp each -> 2632 blocks of 8 warps
    {
        int nwarps = NROWS + KC + KF;
        k_rownorms<<<(nwarps + 7) / 8, 256>>>(feats, ccb, fcb);
    }

    // 2) FMAX padding: 8,650,752 elements
    k_fill_fmax<<<(8650752 + 255) / 256, 256>>>(out);

    // 3) GEMMs
    {
        dim3 gridF(KF / 128, NFEATR / 128);     // (32, 128)
        k_gemm_dist<<<gridF, 256>>>(feats + (size_t)BATCH * D, fcb, out,
                                    NFEATR, KF, /*x2off=*/BATCH, /*e2off=*/KC, 0);
        dim3 gridC(KC / 128, 1);                // (4, 1), M=64 < 128 guarded
        k_gemm_dist<<<gridC, 256>>>(feats, ccb, out,
                                    BATCH, KC, /*x2off=*/0, /*e2off=*/0, 1);
    }

    // 4) argmin + gather + per-row error
    k_argmin_gather<<<NROWS, 256>>>(feats, ccb, fcb, out);

    // 5) scalars
    k_finalize<<<1, 256>>>(out);
}

// round 4
// speedup vs baseline: 2.7607x; 2.7607x over previous
#include <cuda_runtime.h>
#include <cuda_bf16.h>
#include <stdint.h>
#include <math.h>

// ---------------------------------------------------------------------------
// Problem constants
// ---------------------------------------------------------------------------
#define D      768
#define BATCH  64
#define TP1    257
#define TFEAT  256
#define KC     512
#define KF     4096
#define KTOT   4608
#define NROWS  16448
#define NFEATR 16384

#define OFF_QF    1LL
#define OFF_PERP  12632065LL
#define OFF_IDX   12632066LL
#define OFF_DIST  12648514LL

#define FMAXV 3.402823466e+38f

// split-bf16 GEMM config
#define KP     2304            // 3*768
#define CHUNK  64              // bf16 K per smem stage (=128B rows)
#define NCHUNK 36              // KP / CHUNK
#define MT     128
#define NT     128

#define STAGE_BYTES 32768      // A 16KB + B 16KB
#define SMEM_TC     65536      // 2 stages

// ---------------------------------------------------------------------------
// Scratch (device globals -- no runtime allocation allowed)
// ---------------------------------------------------------------------------
__device__ float g_x2[NROWS];
__device__ float g_e2[KTOT];
__device__ float g_rowerr[NROWS];
__device__ int   g_counts[KTOT];
__device__ __nv_bfloat16 g_Abuf[(size_t)NFEATR * KP];  // [a_hi | a_lo | a_hi]
__device__ __nv_bfloat16 g_Bbuf[(size_t)KF * KP];      // [b_hi | b_hi | b_lo]

// ---------------------------------------------------------------------------
// PTX helpers (sm_80-compatible only: ldmatrix / mma.sync / cp.async)
// ---------------------------------------------------------------------------
__device__ __forceinline__ uint32_t smem_u32(const void* p) {
    uint32_t a;
    asm("{ .reg .u64 t; cvta.to.shared.u64 t, %1; cvt.u32.u64 %0, t; }"
        : "=r"(a) : "l"(p));
    return a;
}

#define LDSM_X4(r0, r1, r2, r3, addr) \
    asm volatile("ldmatrix.sync.aligned.m8n8.x4.shared.b16 {%0,%1,%2,%3}, [%4];" \
        : "=r"(r0), "=r"(r1), "=r"(r2), "=r"(r3) : "r"(addr))

#define MMA16816(c, a, b0, b1) \
    asm volatile("mma.sync.aligned.m16n8k16.row.col.f32.bf16.bf16.f32 " \
        "{%0,%1,%2,%3}, {%4,%5,%6,%7}, {%8,%9}, {%0,%1,%2,%3};" \
        : "+f"((c)[0]), "+f"((c)[1]), "+f"((c)[2]), "+f"((c)[3]) \
        : "r"((a)[0]), "r"((a)[1]), "r"((a)[2]), "r"((a)[3]), \
          "r"(b0), "r"(b1))

#define CP_ASYNC16(dst, src) \
    asm volatile("cp.async.cg.shared.global [%0], [%1], 16;" \
        :: "r"(dst), "l"(src) : "memory")
#define CP_COMMIT()  asm volatile("cp.async.commit_group;" ::: "memory")
#define CP_WAIT1()   asm volatile("cp.async.wait_group 1;" ::: "memory")
#define CP_WAIT0()   asm volatile("cp.async.wait_group 0;" ::: "memory")

// ---------------------------------------------------------------------------
// 0) zero counters
// ---------------------------------------------------------------------------
__global__ void k_zero() {
    int i = blockIdx.x * 256 + threadIdx.x;
    if (i < KTOT) g_counts[i] = 0;
}

// ---------------------------------------------------------------------------
// 1) row squared norms: one warp per row
// ---------------------------------------------------------------------------
__global__ void k_rownorms(const float* __restrict__ feats,
                           const float* __restrict__ ccb,
                           const float* __restrict__ fcb) {
    int gw   = (blockIdx.x * blockDim.x + threadIdx.x) >> 5;
    int lane = threadIdx.x & 31;
    if (gw >= NROWS + KC + KF) return;
    const float* p;
    float* o;
    if (gw < NROWS)            { p = feats + (size_t)gw * D;              o = &g_x2[gw]; }
    else if (gw < NROWS + KC)  { p = ccb + (size_t)(gw - NROWS) * D;      o = &g_e2[gw - NROWS]; }
    else                       { p = fcb + (size_t)(gw - NROWS - KC) * D; o = &g_e2[KC + gw - NROWS - KC]; }
    float s = 0.f;
    for (int j = lane; j < D; j += 32) { float v = p[j]; s = fmaf(v, v, s); }
    #pragma unroll
    for (int off = 16; off; off >>= 1) s += __shfl_down_sync(0xFFFFFFFFu, s, off);
    if (lane == 0) *o = s;
}

// ---------------------------------------------------------------------------
// 1b) split fp32 -> (hi, lo) bf16 expansion buffers
// ---------------------------------------------------------------------------
#define APAIRS 6291456   // 16384*768/2
#define BPAIRS 1572864   // 4096*768/2
__global__ void k_split(const float* __restrict__ featsF,
                        const float* __restrict__ fcb) {
    int i = blockIdx.x * 256 + threadIdx.x;
    const float* src;
    uint32_t* dst;
    int o_hi2, o_lo;
    int row, kp;
    if (i < APAIRS) {
        row = i / 384; kp = (i - row * 384) * 2;
        src = featsF + (size_t)row * D + kp;
        dst = (uint32_t*)(g_Abuf + (size_t)row * KP);
        o_lo = 384; o_hi2 = 768;            // A: [hi | lo | hi]
    } else {
        int j = i - APAIRS;
        if (j >= BPAIRS) return;
        row = j / 384; kp = (j - row * 384) * 2;
        src = fcb + (size_t)row * D + kp;
        dst = (uint32_t*)(g_Bbuf + (size_t)row * KP);
        o_lo = 768; o_hi2 = 384;            // B: [hi | hi | lo]
    }
    float2 v = *(const float2*)src;
    __nv_bfloat16 h0 = __float2bfloat16(v.x);
    __nv_bfloat16 h1 = __float2bfloat16(v.y);
    __nv_bfloat16 l0 = __float2bfloat16(v.x - __bfloat162float(h0));
    __nv_bfloat16 l1 = __float2bfloat16(v.y - __bfloat162float(h1));
    uint32_t hp = (uint32_t)__bfloat16_as_ushort(h0) |
                  ((uint32_t)__bfloat16_as_ushort(h1) << 16);
    uint32_t lp = (uint32_t)__bfloat16_as_ushort(l0) |
                  ((uint32_t)__bfloat16_as_ushort(l1) << 16);
    int k2 = kp >> 1;
    dst[k2]         = hp;
    dst[o_lo + k2]  = lp;
    dst[o_hi2 + k2] = hp;
}

// ---------------------------------------------------------------------------
// 2) FMAX padding fill
// ---------------------------------------------------------------------------
__global__ void k_fill_fmax(float* __restrict__ out) {
    float* dist = out + OFF_DIST;
    long long i = (long long)blockIdx.x * 256 + threadIdx.x;
    if (i < 262144LL) {
        int b = (int)(i >> 12);
        int k = KC + (int)(i & 4095);
        dist[(size_t)b * TP1 * KTOT + k] = FMAXV;
        return;
    }
    long long j = i - 262144LL;
    if (j < 8388608LL) {
        int rr = (int)(j >> 9);
        int k  = (int)(j & 511);
        int b  = rr & 63;
        int t  = (rr >> 6) + 1;
        dist[((size_t)b * TP1 + t) * KTOT + k] = FMAXV;
    }
}

// ---------------------------------------------------------------------------
// 3) bf16 HMMA distance GEMM (feature codebook), 128x128 tile, K'=2304
//    dist = x2 + e2 - 2 * (A' @ B'^T), fused epilogue, permuted store.
//    Swizzle: 16B chunk index c at row r lives at (c ^ (r & 7)).
// ---------------------------------------------------------------------------
__global__ __launch_bounds__(256, 2) void k_gemm_tc(float* __restrict__ out) {
    extern __shared__ __align__(1024) char smem[];
    const uint32_t smem_base = smem_u32(smem);
    const int tid  = threadIdx.x;
    const int lane = tid & 31;
    const int wid  = tid >> 5;
    const int wm   = (wid >> 2) * 64;   // warp M offset in tile
    const int wn   = (wid & 3) * 32;    // warp N offset in tile
    const int m0 = blockIdx.y * MT;
    const int n0 = blockIdx.x * NT;

    float acc[4][4][4];
    #pragma unroll
    for (int a = 0; a < 4; a++)
        #pragma unroll
        for (int b = 0; b < 4; b++)
            #pragma unroll
            for (int c = 0; c < 4; c++) acc[a][b][c] = 0.f;

    // per-thread gmem->smem load coords
    const int lrow = tid >> 3;      // 0..31 (+q*32)
    const int lkc  = tid & 7;       // 16B chunk in 128B row

    // prologue: stage 0
    {
        uint32_t sA = smem_base, sB = smem_base + 16384;
        #pragma unroll
        for (int q = 0; q < 4; q++) {
            int r = lrow + q * 32;
            uint32_t off = (uint32_t)r * 128 + (((uint32_t)(lkc ^ (r & 7))) << 4);
            CP_ASYNC16(sA + off, g_Abuf + (size_t)(m0 + r) * KP + lkc * 8);
            CP_ASYNC16(sB + off, g_Bbuf + (size_t)(n0 + r) * KP + lkc * 8);
        }
        CP_COMMIT();
    }

    for (int c = 0; c < NCHUNK; c++) {
        const int s = c & 1;
        if (c + 1 < NCHUNK) {
            const int s2 = (c + 1) & 1;
            const int kb = (c + 1) * CHUNK;
            uint32_t sA = smem_base + s2 * STAGE_BYTES;
            uint32_t sB = sA + 16384;
            #pragma unroll
            for (int q = 0; q < 4; q++) {
                int r = lrow + q * 32;
                uint32_t off = (uint32_t)r * 128 + (((uint32_t)(lkc ^ (r & 7))) << 4);
                CP_ASYNC16(sA + off, g_Abuf + (size_t)(m0 + r) * KP + kb + lkc * 8);
                CP_ASYNC16(sB + off, g_Bbuf + (size_t)(n0 + r) * KP + kb + lkc * 8);
            }
            CP_COMMIT();
            CP_WAIT1();
        } else {
            CP_WAIT0();
        }
        __syncthreads();

        const uint32_t sA = smem_base + s * STAGE_BYTES;
        const uint32_t sB = sA + 16384;
        #pragma unroll
        for (int ks = 0; ks < 4; ks++) {
            uint32_t af[4][4], bf2[2][4];
            #pragma unroll
            for (int mi = 0; mi < 4; mi++) {
                int r   = wm + mi * 16 + (lane & 15);
                int kch = ks * 2 + (lane >> 4);
                uint32_t addr = sA + (uint32_t)r * 128 +
                                (((uint32_t)(kch ^ (r & 7))) << 4);
                LDSM_X4(af[mi][0], af[mi][1], af[mi][2], af[mi][3], addr);
            }
            #pragma unroll
            for (int j = 0; j < 2; j++) {
                int r   = wn + (j * 2 + ((lane >> 4) & 1)) * 8 + (lane & 7);
                int kch = ks * 2 + ((lane >> 3) & 1);
                uint32_t addr = sB + (uint32_t)r * 128 +
                                (((uint32_t)(kch ^ (r & 7))) << 4);
                LDSM_X4(bf2[j][0], bf2[j][1], bf2[j][2], bf2[j][3], addr);
            }
            #pragma unroll
            for (int mi = 0; mi < 4; mi++)
                #pragma unroll
                for (int nb = 0; nb < 4; nb++)
                    MMA16816(acc[mi][nb], af[mi],
                             bf2[nb >> 1][(nb & 1) * 2],
                             bf2[nb >> 1][(nb & 1) * 2 + 1]);
        }
        __syncthreads();
    }

    // fused epilogue: dist = x2 + e2 - 2*acc, permuted [b,t,k] store
    float* dist = out + OFF_DIST;
    #pragma unroll
    for (int mi = 0; mi < 4; mi++) {
        #pragma unroll
        for (int half = 0; half < 2; half++) {
            int m = m0 + wm + mi * 16 + (lane >> 2) + half * 8;
            float xn = g_x2[BATCH + m];
            int t = m >> 6, b = m & 63;
            size_t base = ((size_t)b * TP1 + t + 1) * KTOT + KC;
            #pragma unroll
            for (int nb = 0; nb < 4; nb++) {
                int col = n0 + wn + nb * 8 + 2 * (lane & 3);
                float2 o;
                o.x = xn + g_e2[KC + col]     - 2.f * acc[mi][nb][half * 2];
                o.y = xn + g_e2[KC + col + 1] - 2.f * acc[mi][nb][half * 2 + 1];
                *(float2*)(dist + base + col) = o;
            }
        }
    }
}

// ---------------------------------------------------------------------------
// 3b) fp32 SGEMM for the (tiny) class codebook distances
// ---------------------------------------------------------------------------
__global__ __launch_bounds__(256) void k_gemm_dist(
    const float* __restrict__ A, const float* __restrict__ B,
    float* __restrict__ out, int M, int N, int x2off, int e2off, int isClass)
{
    __shared__ float As[16][128];
    __shared__ float Bs[16][128];
    const int tid = threadIdx.x;
    const int m0 = blockIdx.y * 128;
    const int n0 = blockIdx.x * 128;
    const int ty = tid >> 4, tx = tid & 15;

    float acc[8][8];
    #pragma unroll
    for (int i = 0; i < 8; i++)
        #pragma unroll
        for (int j = 0; j < 8; j++) acc[i][j] = 0.f;

    for (int d0 = 0; d0 < D; d0 += 16) {
        #pragma unroll
        for (int i = 0; i < 2; i++) {
            int lin = tid + i * 256;
            int row = lin >> 2;
            int c4  = (lin & 3) * 4;
            float4 va = make_float4(0.f, 0.f, 0.f, 0.f);
            float4 vb = make_float4(0.f, 0.f, 0.f, 0.f);
            if (m0 + row < M) va = *(const float4*)(A + (size_t)(m0 + row) * D + d0 + c4);
            if (n0 + row < N) vb = *(const float4*)(B + (size_t)(n0 + row) * D + d0 + c4);
            As[c4 + 0][row] = va.x; As[c4 + 1][row] = va.y;
            As[c4 + 2][row] = va.z; As[c4 + 3][row] = va.w;
            Bs[c4 + 0][row] = vb.x; Bs[c4 + 1][row] = vb.y;
            Bs[c4 + 2][row] = vb.z; Bs[c4 + 3][row] = vb.w;
        }
        __syncthreads();
        #pragma unroll
        for (int d = 0; d < 16; d++) {
            float4 a0 = *(const float4*)&As[d][ty * 8];
            float4 a1 = *(const float4*)&As[d][ty * 8 + 4];
            float4 b0 = *(const float4*)&Bs[d][tx * 8];
            float4 b1 = *(const float4*)&Bs[d][tx * 8 + 4];
            float ra[8] = {a0.x, a0.y, a0.z, a0.w, a1.x, a1.y, a1.z, a1.w};
            float rb[8] = {b0.x, b0.y, b0.z, b0.w, b1.x, b1.y, b1.z, b1.w};
            #pragma unroll
            for (int i = 0; i < 8; i++)
                #pragma unroll
                for (int j = 0; j < 8; j++)
                    acc[i][j] = fmaf(ra[i], rb[j], acc[i][j]);
        }
        __syncthreads();
    }

    float* dist = out + OFF_DIST;
    #pragma unroll
    for (int i = 0; i < 8; i++) {
        int n = m0 + ty * 8 + i;
        if (n >= M) return;
        float xn = g_x2[x2off + n];
        size_t base;
        if (isClass) {
            base = (size_t)n * TP1 * KTOT;
        } else {
            int t = n >> 6, b = n & 63;
            base = ((size_t)b * TP1 + (t + 1)) * KTOT + KC;
        }
        #pragma unroll
        for (int j2 = 0; j2 < 4; j2++) {
            int k = n0 + tx * 8 + j2 * 2;
            float2 o;
            o.x = xn + g_e2[e2off + k]     - 2.f * acc[i][j2 * 2];
            o.y = xn + g_e2[e2off + k + 1] - 2.f * acc[i][j2 * 2 + 1];
            *(float2*)(dist + base + k) = o;
        }
    }
}

// ---------------------------------------------------------------------------
// 4) per-row argmin + gather + per-row sq-error
// ---------------------------------------------------------------------------
__global__ __launch_bounds__(256) void k_argmin_gather(
    const float* __restrict__ feats,
    const float* __restrict__ ccb,
    const float* __restrict__ fcb,
    float* __restrict__ out)
{
    const int r = blockIdx.x;
    const int tid = threadIdx.x;
    const float* dist = out + OFF_DIST;

    const float* rowp; const float* cb;
    int K, flatrow, idx_add;
    if (r < BATCH) {
        K = KC; rowp = dist + (size_t)r * TP1 * KTOT;
        cb = ccb; flatrow = r; idx_add = 0;
    } else {
        int rr = r - BATCH;
        int t = rr >> 6, b = rr & 63;
        K = KF; rowp = dist + ((size_t)b * TP1 + (t + 1)) * KTOT + KC;
        cb = fcb; flatrow = BATCH + rr; idx_add = KC;
    }

    float best = FMAXV;
    int bidx = K;
    for (int k = tid; k < K; k += 256) {
        float v = rowp[k];
        if (v < best) { best = v; bidx = k; }
    }

    __shared__ float sv[256];
    __shared__ int   si[256];
    sv[tid] = best; si[tid] = bidx;
    __syncthreads();
    #pragma unroll
    for (int s = 128; s > 0; s >>= 1) {
        if (tid < s) {
            float v2 = sv[tid + s]; int i2 = si[tid + s];
            if (v2 < sv[tid] || (v2 == sv[tid] && i2 < si[tid])) { sv[tid] = v2; si[tid] = i2; }
        }
        __syncthreads();
    }
    const int li = si[0];

    const float* code = cb + (size_t)li * D;
    const float* x    = feats + (size_t)flatrow * D;
    float* qf = out + OFF_QF + (size_t)flatrow * D;
    float err = 0.f;
    for (int d = tid; d < D; d += 256) {
        float c = code[d];
        qf[d] = c;
        float dd = c - x[d];
        err = fmaf(dd, dd, err);
    }
    __shared__ float se[256];
    se[tid] = err;
    __syncthreads();
    #pragma unroll
    for (int s = 128; s > 0; s >>= 1) {
        if (tid < s) se[tid] += se[tid + s];
        __syncthreads();
    }
    if (tid == 0) {
        g_rowerr[r] = se[0];
        out[OFF_IDX + r] = (float)(li + idx_add);
        atomicAdd(&g_counts[idx_add + li], 1);
    }
}

// ---------------------------------------------------------------------------
// 5) finalize loss + perplexity
// ---------------------------------------------------------------------------
__global__ __launch_bounds__(256) void k_finalize(float* __restrict__ out) {
    __shared__ double sh[256];
    const int tid = threadIdx.x;
    double res[4];

    for (int pass = 0; pass < 4; pass++) {
        double s = 0.0;
        if (pass == 0) {
            for (int r = tid; r < BATCH; r += 256) s += (double)g_rowerr[r];
        } else if (pass == 1) {
            for (int r = BATCH + tid; r < NROWS; r += 256) s += (double)g_rowerr[r];
        } else if (pass == 2) {
            for (int k = tid; k < KC; k += 256) {
                double p = (double)g_counts[k] / (double)BATCH;
                s += p * log(p + 1e-10);
            }
        } else {
            for (int k = tid; k < KF; k += 256) {
                double p = (double)g_counts[KC + k] / (double)NFEATR;
                s += p * log(p + 1e-10);
            }
        }
        sh[tid] = s;
        __syncthreads();
        for (int st = 128; st > 0; st >>= 1) {
            if (tid < st) sh[tid] += sh[tid + st];
            __syncthreads();
        }
        res[pass] = sh[0];
        __syncthreads();
    }

    if (tid == 0) {
        double mean_c = res[0] / (double)(1 * BATCH * D);
        double mean_f = res[1] / (double)(TFEAT * BATCH * D);
        out[0]        = (float)(0.25 * (mean_c + mean_f));
        out[OFF_PERP] = (float)(exp(-res[2]) + exp(-res[3]));
    }
}

// ---------------------------------------------------------------------------
// Launch
// ---------------------------------------------------------------------------
extern "C" void kernel_launch(void* const* d_in, const int* in_sizes, int n_in,
                              void* d_out, int out_size) {
    const float* feats = (const float*)d_in[0];
    const float* ccb   = (const float*)d_in[1];
    const float* fcb   = (const float*)d_in[2];
    float* out = (float*)d_out;

    static bool attr_set = false;
    if (!attr_set) {
        cudaFuncSetAttribute(k_gemm_tc,
                             cudaFuncAttributeMaxDynamicSharedMemorySize, SMEM_TC);
        attr_set = true;
    }

    k_zero<<<(KTOT + 255) / 256, 256>>>();

    {
        int nwarps = NROWS + KC + KF;
        k_rownorms<<<(nwarps + 7) / 8, 256>>>(feats, ccb, fcb);
    }

    k_split<<<(APAIRS + BPAIRS + 255) / 256, 256>>>(feats + (size_t)BATCH * D, fcb);

    k_fill_fmax<<<(8650752 + 255) / 256, 256>>>(out);

    // HMMA feature GEMM: grid.x = N tiles (x fastest -> consecutive CTAs share A tile)
    {
        dim3 grid(KF / NT, NFEATR / MT);   // (32, 128)
        k_gemm_tc<<<grid, 256, SMEM_TC>>>(out);
    }

    // class GEMM (tiny) on fp32 path
    {
        dim3 gridC(KC / 128, 1);
        k_gemm_dist<<<gridC, 256>>>(feats, ccb, out, BATCH, KC, 0, 0, 1);
    }

    k_argmin_gather<<<NROWS, 256>>>(feats, ccb, fcb, out);
    k_finalize<<<1, 256>>>(out);
}